// round 4
// baseline (speedup 1.0000x reference)
#include <cuda_runtime.h>
#include <cuda_bf16.h>
#include <cstdint>

static constexpr int T_TOK = 8192;
static constexpr int C_DIM = 2048;
static constexpr int K3 = 3 * C_DIM;       // 6144
static constexpr int BM = 128;
static constexpr int BN = 256;
static constexpr int BK = 64;              // bf16 per K-chunk
static constexpr int NKCH = K3 / BK;       // 96
static constexpr int ROW_BYTES = 144;      // 128B data + 16B pad (bank-conflict-free)
static constexpr int AROWS = BM;
static constexpr int STAGE_ROWS = BM + BN; // 384
static constexpr int STAGE_BYTES = STAGE_ROWS * ROW_BYTES;  // 55296
static constexpr int STAGES = 4;
static constexpr int GEMM_SMEM = STAGES * STAGE_BYTES;      // 221184

// -------- scratch (static __device__; no allocation allowed) --------
__device__ __nv_bfloat16 g_xs [(size_t)T_TOK * K3];
__device__ __nv_bfloat16 g_ys [(size_t)T_TOK * K3];
__device__ __nv_bfloat16 g_aos[(size_t)T_TOK * K3];
__device__ __nv_bfloat16 g_wq [(size_t)C_DIM * K3];
__device__ __nv_bfloat16 g_wkv[(size_t)(2 * C_DIM) * K3];
__device__ __nv_bfloat16 g_wo [(size_t)C_DIM * K3];
__device__ float g_q  [(size_t)T_TOK * C_DIM];
__device__ float g_kv [(size_t)T_TOK * 2 * C_DIM];
__device__ float g_ao [(size_t)T_TOK * C_DIM];
__device__ float g_bkv[2 * C_DIM];

// -------- PTX helpers (sm_80+ only; no 'a'-suffix features) --------
__device__ __forceinline__ uint32_t smem_u32(const void* p) {
    uint32_t a;
    asm("{ .reg .u64 t; cvta.to.shared.u64 t, %1; cvt.u32.u64 %0, t; }" : "=r"(a) : "l"(p));
    return a;
}
#define CP_ASYNC16(s, g) \
    asm volatile("cp.async.cg.shared.global [%0], [%1], 16;" :: "r"((uint32_t)(s)), "l"(g) : "memory")
#define CP_COMMIT() asm volatile("cp.async.commit_group;" ::: "memory")

#define LDSM4(r, addr) \
    asm volatile("ldmatrix.sync.aligned.m8n8.x4.shared.b16 {%0,%1,%2,%3}, [%4];" \
        : "=r"((r)[0]), "=r"((r)[1]), "=r"((r)[2]), "=r"((r)[3]) : "r"(addr))

#define MMA16816(d, a, b0, b1) \
    asm volatile("mma.sync.aligned.m16n8k16.row.col.f32.bf16.bf16.f32 " \
        "{%0,%1,%2,%3}, {%4,%5,%6,%7}, {%8,%9}, {%0,%1,%2,%3};" \
        : "+f"((d)[0]), "+f"((d)[1]), "+f"((d)[2]), "+f"((d)[3]) \
        : "r"((a)[0]), "r"((a)[1]), "r"((a)[2]), "r"((a)[3]), "r"(b0), "r"(b1))

// -------- split conversions: fp32 -> [hi|hi|lo] (act) / [hi|lo|hi] (wgt) --------
__global__ void split_act_kernel(const float* __restrict__ src,
                                 __nv_bfloat16* __restrict__ dst) {
    size_t i = (size_t)blockIdx.x * blockDim.x + threadIdx.x;
    int r = (int)(i >> 11);
    int c = (int)(i & (C_DIM - 1));
    float v = src[i];
    __nv_bfloat16 hi = __float2bfloat16_rn(v);
    __nv_bfloat16 lo = __float2bfloat16_rn(v - __bfloat162float(hi));
    size_t o = (size_t)r * K3 + c;
    dst[o] = hi; dst[o + C_DIM] = hi; dst[o + 2 * C_DIM] = lo;
}
__global__ void split_wgt_kernel(const float* __restrict__ src,
                                 __nv_bfloat16* __restrict__ dst) {
    size_t i = (size_t)blockIdx.x * blockDim.x + threadIdx.x;
    int r = (int)(i >> 11);
    int c = (int)(i & (C_DIM - 1));
    float v = src[i];
    __nv_bfloat16 hi = __float2bfloat16_rn(v);
    __nv_bfloat16 lo = __float2bfloat16_rn(v - __bfloat162float(hi));
    size_t o = (size_t)r * K3 + c;
    dst[o] = hi; dst[o + C_DIM] = lo; dst[o + 2 * C_DIM] = hi;
}
__global__ void concat_bias_kernel(const float* __restrict__ bk,
                                   const float* __restrict__ bv,
                                   float* __restrict__ dst) {
    int i = blockIdx.x * blockDim.x + threadIdx.x;
    dst[i] = (i < C_DIM) ? bk[i] : bv[i - C_DIM];
}

// -------- HMMA GEMM: C[M,N] = A[M,K3] @ B[N,K3]^T + bias (+residual) --------
__device__ __forceinline__ void load_tiles(const __nv_bfloat16* __restrict__ A,
                                           const __nv_bfloat16* __restrict__ B,
                                           int rowA0, int rowB0, int k0,
                                           uint32_t sbase, int tid) {
#pragma unroll
    for (int i = 0; i < 12; i++) {          // 3072 x 16B chunks / 256 threads
        int idx = i * 256 + tid;
        int row = idx >> 3;
        int c = idx & 7;
        const __nv_bfloat16* g = (row < AROWS)
            ? A + (size_t)(rowA0 + row) * K3 + (k0 + c * 8)
            : B + (size_t)(rowB0 + row - AROWS) * K3 + (k0 + c * 8);
        CP_ASYNC16(sbase + row * ROW_BYTES + c * 16, g);
    }
}

__global__ void __launch_bounds__(256, 1)
gemm_kernel(const __nv_bfloat16* __restrict__ A, const __nv_bfloat16* __restrict__ B,
            const float* __restrict__ bias, const float* __restrict__ residual,
            float* __restrict__ Cout, int ldc) {
    extern __shared__ __align__(16) char smem[];
    uint32_t sb = smem_u32(smem);
    int tid = threadIdx.x;
    int wid = tid >> 5, lid = tid & 31;
    int warp_m = wid & 1;                   // 2 warps over M
    int warp_n = wid >> 1;                  // 4 warps over N
    int rowA0 = blockIdx.y * BM, rowB0 = blockIdx.x * BN;

    float acc[4][8][4];
#pragma unroll
    for (int mi = 0; mi < 4; mi++)
#pragma unroll
        for (int ni = 0; ni < 8; ni++)
#pragma unroll
            for (int e = 0; e < 4; e++) acc[mi][ni][e] = 0.f;

    // prologue: fill STAGES-1 stages
#pragma unroll
    for (int s = 0; s < STAGES - 1; s++) {
        load_tiles(A, B, rowA0, rowB0, s * BK, sb + s * STAGE_BYTES, tid);
        CP_COMMIT();
    }

    // ldmatrix lane base addresses
    // A frag (16x16): lanes 0-15 -> rows 0..15 @k0; 16-31 -> rows 0..15 @k+8
    uint32_t a_base = sb + (warp_m * 64 + (lid & 15)) * ROW_BYTES + ((lid >> 4) << 4);
    // B frag pair (16 n-rows x k16): g=lane>>3: g0 rows+0 k0, g1 rows+0 k8, g2 rows+8 k0, g3 rows+8 k8
    int g = lid >> 3;
    uint32_t b_base = sb + (AROWS + warp_n * 64 + ((g >> 1) << 3) + (lid & 7)) * ROW_BYTES
                         + ((g & 1) << 4);

    for (int k = 0; k < NKCH; k++) {
        int rem = NKCH - 1 - k;
        if (rem > STAGES - 2) rem = STAGES - 2;
        switch (rem) {
            case 0: asm volatile("cp.async.wait_group 0;" ::: "memory"); break;
            case 1: asm volatile("cp.async.wait_group 1;" ::: "memory"); break;
            default: asm volatile("cp.async.wait_group 2;" ::: "memory"); break;
        }
        __syncthreads();

        int pk = k + STAGES - 1;
        if (pk < NKCH) {
            load_tiles(A, B, rowA0, rowB0, pk * BK, sb + (pk % STAGES) * STAGE_BYTES, tid);
            CP_COMMIT();
        }

        uint32_t sa = a_base + (k % STAGES) * STAGE_BYTES;
        uint32_t sbb = b_base + (k % STAGES) * STAGE_BYTES;
#pragma unroll
        for (int ks = 0; ks < 4; ks++) {    // 4 x k16 per BK=64
            uint32_t afr[4][4], bfr[4][4];
#pragma unroll
            for (int mi = 0; mi < 4; mi++)
                LDSM4(afr[mi], sa + mi * 16 * ROW_BYTES + ks * 32);
#pragma unroll
            for (int ni2 = 0; ni2 < 4; ni2++)
                LDSM4(bfr[ni2], sbb + ni2 * 16 * ROW_BYTES + ks * 32);
#pragma unroll
            for (int mi = 0; mi < 4; mi++)
#pragma unroll
                for (int ni2 = 0; ni2 < 4; ni2++) {
                    MMA16816(acc[mi][2 * ni2],     afr[mi], bfr[ni2][0], bfr[ni2][1]);
                    MMA16816(acc[mi][2 * ni2 + 1], afr[mi], bfr[ni2][2], bfr[ni2][3]);
                }
        }
    }

    // epilogue: d0,d1 -> row l/4; d2,d3 -> row l/4+8; cols (l%4)*2..+1
    int qrow = lid >> 2, qcol = (lid & 3) * 2;
#pragma unroll
    for (int mi = 0; mi < 4; mi++) {
#pragma unroll
        for (int ni = 0; ni < 8; ni++) {
            int r0 = rowA0 + warp_m * 64 + mi * 16 + qrow;
            int col = rowB0 + warp_n * 64 + ni * 8 + qcol;
            float2 bb = *(const float2*)(bias + col);
            float2 v0 = make_float2(acc[mi][ni][0] + bb.x, acc[mi][ni][1] + bb.y);
            float2 v1 = make_float2(acc[mi][ni][2] + bb.x, acc[mi][ni][3] + bb.y);
            if (residual) {
                float2 r0v = *(const float2*)(residual + (size_t)r0 * ldc + col);
                float2 r1v = *(const float2*)(residual + (size_t)(r0 + 8) * ldc + col);
                v0.x += r0v.x; v0.y += r0v.y;
                v1.x += r1v.x; v1.y += r1v.y;
            }
            *(float2*)(Cout + (size_t)r0 * ldc + col) = v0;
            *(float2*)(Cout + (size_t)(r0 + 8) * ldc + col) = v1;
        }
    }
}

// -------- per-token [8x8] head-mixing attention; one warp per token --------
__global__ void __launch_bounds__(256)
attention_kernel(const float* __restrict__ Q, const float* __restrict__ KV,
                 float* __restrict__ AO) {
    int lid = threadIdx.x & 31;
    int t = blockIdx.x * 8 + (threadIdx.x >> 5);
    const float4* q  = (const float4*)(Q  + (size_t)t * C_DIM);
    const float4* kv = (const float4*)(KV + (size_t)t * 2 * C_DIM);
    float4* ao = (float4*)(AO + (size_t)t * C_DIM);
    const float scale = 0.0625f;  // 256^-0.5

    for (int h = 0; h < 8; h++) {
        float4 q0 = q[h * 64 + lid * 2];
        float4 q1 = q[h * 64 + lid * 2 + 1];
        float s[8];
#pragma unroll
        for (int gg = 0; gg < 8; gg++) {
            float4 k0 = kv[gg * 64 + lid * 2];
            float4 k1 = kv[gg * 64 + lid * 2 + 1];
            float d = q0.x * k0.x + q0.y * k0.y + q0.z * k0.z + q0.w * k0.w
                    + q1.x * k1.x + q1.y * k1.y + q1.z * k1.z + q1.w * k1.w;
#pragma unroll
            for (int off = 16; off >= 1; off >>= 1)
                d += __shfl_xor_sync(0xffffffffu, d, off);
            s[gg] = d * scale;
        }
        float m = s[0];
#pragma unroll
        for (int gg = 1; gg < 8; gg++) m = fmaxf(m, s[gg]);
        float e[8], sum = 0.f;
#pragma unroll
        for (int gg = 0; gg < 8; gg++) { e[gg] = __expf(s[gg] - m); sum += e[gg]; }
        float inv = 1.f / sum;
        float4 a0 = make_float4(0.f, 0.f, 0.f, 0.f);
        float4 a1 = make_float4(0.f, 0.f, 0.f, 0.f);
#pragma unroll
        for (int gg = 0; gg < 8; gg++) {
            float p = e[gg] * inv;
            float4 v0 = kv[512 + gg * 64 + lid * 2];
            float4 v1 = kv[512 + gg * 64 + lid * 2 + 1];
            a0.x += p * v0.x; a0.y += p * v0.y; a0.z += p * v0.z; a0.w += p * v0.w;
            a1.x += p * v1.x; a1.y += p * v1.y; a1.z += p * v1.z; a1.w += p * v1.w;
        }
        ao[h * 64 + lid * 2] = a0;
        ao[h * 64 + lid * 2 + 1] = a1;
    }
}

// -------- launch --------
extern "C" void kernel_launch(void* const* d_in, const int* in_sizes, int n_in,
                              void* d_out, int out_size) {
    (void)in_sizes; (void)n_in; (void)out_size;
    const float* x  = (const float*)d_in[0];
    const float* y  = (const float*)d_in[1];
    const float* Wq = (const float*)d_in[2];
    const float* bq = (const float*)d_in[3];
    const float* Wk = (const float*)d_in[4];
    const float* bk = (const float*)d_in[5];
    const float* Wv = (const float*)d_in[6];
    const float* bv = (const float*)d_in[7];
    const float* Wo = (const float*)d_in[8];
    const float* bo = (const float*)d_in[9];
    float* out = (float*)d_out;

    cudaFuncSetAttribute(gemm_kernel, cudaFuncAttributeMaxDynamicSharedMemorySize, GEMM_SMEM);

    __nv_bfloat16 *xs, *ys, *aos, *wq, *wkv, *wo;
    float *q, *kv, *ao, *bkv;
    cudaGetSymbolAddress((void**)&xs,  g_xs);
    cudaGetSymbolAddress((void**)&ys,  g_ys);
    cudaGetSymbolAddress((void**)&aos, g_aos);
    cudaGetSymbolAddress((void**)&wq,  g_wq);
    cudaGetSymbolAddress((void**)&wkv, g_wkv);
    cudaGetSymbolAddress((void**)&wo,  g_wo);
    cudaGetSymbolAddress((void**)&q,   g_q);
    cudaGetSymbolAddress((void**)&kv,  g_kv);
    cudaGetSymbolAddress((void**)&ao,  g_ao);
    cudaGetSymbolAddress((void**)&bkv, g_bkv);

    const int actBlocks = (T_TOK * C_DIM) / 256;   // 65536
    const int wgtBlocks = (C_DIM * C_DIM) / 256;   // 16384

    split_act_kernel<<<actBlocks, 256>>>(x, xs);
    split_act_kernel<<<actBlocks, 256>>>(y, ys);
    split_wgt_kernel<<<wgtBlocks, 256>>>(Wq, wq);
    split_wgt_kernel<<<wgtBlocks, 256>>>(Wk, wkv);
    split_wgt_kernel<<<wgtBlocks, 256>>>(Wv, wkv + (size_t)C_DIM * K3);
    split_wgt_kernel<<<wgtBlocks, 256>>>(Wo, wo);
    concat_bias_kernel<<<16, 256>>>(bk, bv, bkv);

    dim3 gq(C_DIM / BN, T_TOK / BM);        // (8, 64)
    gemm_kernel<<<gq, 256, GEMM_SMEM>>>(xs, wq, bq, nullptr, q, C_DIM);
    dim3 gkv(2 * C_DIM / BN, T_TOK / BM);   // (16, 64)
    gemm_kernel<<<gkv, 256, GEMM_SMEM>>>(ys, wkv, bkv, nullptr, kv, 2 * C_DIM);

    attention_kernel<<<T_TOK / 8, 256>>>(q, kv, ao);

    split_act_kernel<<<actBlocks, 256>>>(ao, aos);
    gemm_kernel<<<gq, 256, GEMM_SMEM>>>(aos, wo, bo, x, out, C_DIM);
}

// round 5
// speedup vs baseline: 1.0506x; 1.0506x over previous
#include <cuda_runtime.h>
#include <cuda_bf16.h>
#include <cstdint>

static constexpr int T_TOK = 8192;
static constexpr int C_DIM = 2048;
static constexpr int K3 = 3 * C_DIM;       // 6144
static constexpr int BM = 128;
static constexpr int BN = 256;
static constexpr int BK = 64;              // bf16 per K-chunk
static constexpr int NKCH = K3 / BK;       // 96
static constexpr int ROW_BYTES = 144;      // 128B data + 16B pad (conflict-free ldmatrix)
static constexpr int AROWS = BM;
static constexpr int STAGE_ROWS = BM + BN; // 384
static constexpr int STAGE_BYTES = STAGE_ROWS * ROW_BYTES;  // 55296
static constexpr int STAGES = 4;
static constexpr int GEMM_SMEM = STAGES * STAGE_BYTES;      // 221184

// -------- scratch (static __device__; no allocation allowed) --------
__device__ __nv_bfloat16 g_xs [(size_t)T_TOK * K3];
__device__ __nv_bfloat16 g_ys [(size_t)T_TOK * K3];
__device__ __nv_bfloat16 g_aos[(size_t)T_TOK * K3];
__device__ __nv_bfloat16 g_wq [(size_t)C_DIM * K3];
__device__ __nv_bfloat16 g_wkv[(size_t)(2 * C_DIM) * K3];
__device__ __nv_bfloat16 g_wo [(size_t)C_DIM * K3];
__device__ float g_q  [(size_t)T_TOK * C_DIM];
__device__ float g_kv [(size_t)T_TOK * 2 * C_DIM];
__device__ float g_bkv[2 * C_DIM];

// -------- PTX helpers (sm_80+ only; no 'a'-suffix features) --------
__device__ __forceinline__ uint32_t smem_u32(const void* p) {
    uint32_t a;
    asm("{ .reg .u64 t; cvta.to.shared.u64 t, %1; cvt.u32.u64 %0, t; }" : "=r"(a) : "l"(p));
    return a;
}
#define CP_ASYNC16(s, g) \
    asm volatile("cp.async.cg.shared.global [%0], [%1], 16;" :: "r"((uint32_t)(s)), "l"(g) : "memory")
#define CP_COMMIT() asm volatile("cp.async.commit_group;" ::: "memory")

#define LDSM4(r, addr) \
    asm volatile("ldmatrix.sync.aligned.m8n8.x4.shared.b16 {%0,%1,%2,%3}, [%4];" \
        : "=r"((r)[0]), "=r"((r)[1]), "=r"((r)[2]), "=r"((r)[3]) : "r"(addr))

#define MMA16816(d, a, b0, b1) \
    asm volatile("mma.sync.aligned.m16n8k16.row.col.f32.bf16.bf16.f32 " \
        "{%0,%1,%2,%3}, {%4,%5,%6,%7}, {%8,%9}, {%0,%1,%2,%3};" \
        : "+f"((d)[0]), "+f"((d)[1]), "+f"((d)[2]), "+f"((d)[3]) \
        : "r"((a)[0]), "r"((a)[1]), "r"((a)[2]), "r"((a)[3]), "r"(b0), "r"(b1))

__device__ __forceinline__ uint32_t pack_bf16x2(float x, float y) {
    __nv_bfloat162 h = __floats2bfloat162_rn(x, y);
    return *(uint32_t*)&h;
}

// -------- split conversions: fp32 -> [hi|hi|lo] (act) / [hi|lo|hi] (wgt) --------
__global__ void split_act_kernel(const float* __restrict__ src,
                                 __nv_bfloat16* __restrict__ dst) {
    size_t i = (size_t)blockIdx.x * blockDim.x + threadIdx.x;
    int r = (int)(i >> 11);
    int c = (int)(i & (C_DIM - 1));
    float v = src[i];
    __nv_bfloat16 hi = __float2bfloat16_rn(v);
    __nv_bfloat16 lo = __float2bfloat16_rn(v - __bfloat162float(hi));
    size_t o = (size_t)r * K3 + c;
    dst[o] = hi; dst[o + C_DIM] = hi; dst[o + 2 * C_DIM] = lo;
}
__global__ void split_wgt_kernel(const float* __restrict__ src,
                                 __nv_bfloat16* __restrict__ dst) {
    size_t i = (size_t)blockIdx.x * blockDim.x + threadIdx.x;
    int r = (int)(i >> 11);
    int c = (int)(i & (C_DIM - 1));
    float v = src[i];
    __nv_bfloat16 hi = __float2bfloat16_rn(v);
    __nv_bfloat16 lo = __float2bfloat16_rn(v - __bfloat162float(hi));
    size_t o = (size_t)r * K3 + c;
    dst[o] = hi; dst[o + C_DIM] = lo; dst[o + 2 * C_DIM] = hi;
}
__global__ void concat_bias_kernel(const float* __restrict__ bk,
                                   const float* __restrict__ bv,
                                   float* __restrict__ dst) {
    int i = blockIdx.x * blockDim.x + threadIdx.x;
    dst[i] = (i < C_DIM) ? bk[i] : bv[i - C_DIM];
}

// -------- HMMA GEMM: C[M,N] = A[M,K3] @ B[N,K3]^T + bias (+residual) --------
__device__ __forceinline__ void load_tiles(const __nv_bfloat16* __restrict__ A,
                                           const __nv_bfloat16* __restrict__ B,
                                           int rowA0, int rowB0, int k0,
                                           uint32_t sbase, int tid) {
#pragma unroll
    for (int i = 0; i < 12; i++) {          // 3072 x 16B chunks / 256 threads
        int idx = i * 256 + tid;
        int row = idx >> 3;
        int c = idx & 7;
        const __nv_bfloat16* g = (row < AROWS)
            ? A + (size_t)(rowA0 + row) * K3 + (k0 + c * 8)
            : B + (size_t)(rowB0 + row - AROWS) * K3 + (k0 + c * 8);
        CP_ASYNC16(sbase + row * ROW_BYTES + c * 16, g);
    }
}

__global__ void __launch_bounds__(256, 1)
gemm_kernel(const __nv_bfloat16* __restrict__ A, const __nv_bfloat16* __restrict__ B,
            const float* __restrict__ bias, const float* __restrict__ residual,
            float* __restrict__ Cout, int ldc) {
    extern __shared__ __align__(16) char smem[];
    uint32_t sb = smem_u32(smem);
    int tid = threadIdx.x;
    int wid = tid >> 5, lid = tid & 31;
    int warp_m = wid & 1;                   // 2 warps over M
    int warp_n = wid >> 1;                  // 4 warps over N
    int rowA0 = blockIdx.y * BM, rowB0 = blockIdx.x * BN;

    float acc[4][8][4];
#pragma unroll
    for (int mi = 0; mi < 4; mi++)
#pragma unroll
        for (int ni = 0; ni < 8; ni++)
#pragma unroll
            for (int e = 0; e < 4; e++) acc[mi][ni][e] = 0.f;

    // prologue: fill STAGES-1 stages
#pragma unroll
    for (int s = 0; s < STAGES - 1; s++) {
        load_tiles(A, B, rowA0, rowB0, s * BK, sb + s * STAGE_BYTES, tid);
        CP_COMMIT();
    }

    // ldmatrix lane base addresses
    uint32_t a_base = sb + (warp_m * 64 + (lid & 15)) * ROW_BYTES + ((lid >> 4) << 4);
    int g = lid >> 3;
    uint32_t b_base = sb + (AROWS + warp_n * 64 + ((g >> 1) << 3) + (lid & 7)) * ROW_BYTES
                         + ((g & 1) << 4);

    for (int k = 0; k < NKCH; k++) {
        int rem = NKCH - 1 - k;
        if (rem > STAGES - 2) rem = STAGES - 2;
        switch (rem) {
            case 0: asm volatile("cp.async.wait_group 0;" ::: "memory"); break;
            case 1: asm volatile("cp.async.wait_group 1;" ::: "memory"); break;
            default: asm volatile("cp.async.wait_group 2;" ::: "memory"); break;
        }
        __syncthreads();

        uint32_t sa  = a_base + (k % STAGES) * STAGE_BYTES;
        uint32_t sbb = b_base + (k % STAGES) * STAGE_BYTES;

        // double-buffered fragments across ks-steps
        uint32_t afr[2][4][4], bfr[2][4][4];
#pragma unroll
        for (int mi = 0; mi < 4; mi++) LDSM4(afr[0][mi], sa + mi * 16 * ROW_BYTES);
#pragma unroll
        for (int ni2 = 0; ni2 < 4; ni2++) LDSM4(bfr[0][ni2], sbb + ni2 * 16 * ROW_BYTES);

        // prefetch next stage after the first fragment batch is in flight
        int pk = k + STAGES - 1;
        if (pk < NKCH) {
            load_tiles(A, B, rowA0, rowB0, pk * BK, sb + (pk % STAGES) * STAGE_BYTES, tid);
            CP_COMMIT();
        }

#pragma unroll
        for (int ks = 0; ks < 4; ks++) {    // 4 x k16 per BK=64
            int cur = ks & 1, nxt = cur ^ 1;
            if (ks < 3) {
#pragma unroll
                for (int mi = 0; mi < 4; mi++)
                    LDSM4(afr[nxt][mi], sa + mi * 16 * ROW_BYTES + (ks + 1) * 32);
#pragma unroll
                for (int ni2 = 0; ni2 < 4; ni2++)
                    LDSM4(bfr[nxt][ni2], sbb + ni2 * 16 * ROW_BYTES + (ks + 1) * 32);
            }
#pragma unroll
            for (int mi = 0; mi < 4; mi++)
#pragma unroll
                for (int ni2 = 0; ni2 < 4; ni2++) {
                    MMA16816(acc[mi][2 * ni2],     afr[cur][mi], bfr[cur][ni2][0], bfr[cur][ni2][1]);
                    MMA16816(acc[mi][2 * ni2 + 1], afr[cur][mi], bfr[cur][ni2][2], bfr[cur][ni2][3]);
                }
        }
    }

    // epilogue
    int qrow = lid >> 2, qcol = (lid & 3) * 2;
#pragma unroll
    for (int mi = 0; mi < 4; mi++) {
#pragma unroll
        for (int ni = 0; ni < 8; ni++) {
            int r0 = rowA0 + warp_m * 64 + mi * 16 + qrow;
            int col = rowB0 + warp_n * 64 + ni * 8 + qcol;
            float2 bb = *(const float2*)(bias + col);
            float2 v0 = make_float2(acc[mi][ni][0] + bb.x, acc[mi][ni][1] + bb.y);
            float2 v1 = make_float2(acc[mi][ni][2] + bb.x, acc[mi][ni][3] + bb.y);
            if (residual) {
                float2 r0v = *(const float2*)(residual + (size_t)r0 * ldc + col);
                float2 r1v = *(const float2*)(residual + (size_t)(r0 + 8) * ldc + col);
                v0.x += r0v.x; v0.y += r0v.y;
                v1.x += r1v.x; v1.y += r1v.y;
            }
            *(float2*)(Cout + (size_t)r0 * ldc + col) = v0;
            *(float2*)(Cout + (size_t)(r0 + 8) * ldc + col) = v1;
        }
    }
}

// -------- per-token [8x8] head-mixing attention; writes split bf16 directly --------
__global__ void __launch_bounds__(256)
attention_kernel(const float* __restrict__ Q, const float* __restrict__ KV,
                 __nv_bfloat16* __restrict__ AOS) {
    int lid = threadIdx.x & 31;
    int t = blockIdx.x * 8 + (threadIdx.x >> 5);
    const float4* q  = (const float4*)(Q  + (size_t)t * C_DIM);
    const float4* kv = (const float4*)(KV + (size_t)t * 2 * C_DIM);
    const float scale = 0.0625f;  // 256^-0.5

    for (int h = 0; h < 8; h++) {
        float4 q0 = q[h * 64 + lid * 2];
        float4 q1 = q[h * 64 + lid * 2 + 1];
        float s[8];
#pragma unroll
        for (int gg = 0; gg < 8; gg++) {
            float4 k0 = kv[gg * 64 + lid * 2];
            float4 k1 = kv[gg * 64 + lid * 2 + 1];
            float d = q0.x * k0.x + q0.y * k0.y + q0.z * k0.z + q0.w * k0.w
                    + q1.x * k1.x + q1.y * k1.y + q1.z * k1.z + q1.w * k1.w;
#pragma unroll
            for (int off = 16; off >= 1; off >>= 1)
                d += __shfl_xor_sync(0xffffffffu, d, off);
            s[gg] = d * scale;
        }
        float m = s[0];
#pragma unroll
        for (int gg = 1; gg < 8; gg++) m = fmaxf(m, s[gg]);
        float e[8], sum = 0.f;
#pragma unroll
        for (int gg = 0; gg < 8; gg++) { e[gg] = __expf(s[gg] - m); sum += e[gg]; }
        float inv = 1.f / sum;
        float f[8];
#pragma unroll
        for (int j = 0; j < 8; j++) f[j] = 0.f;
#pragma unroll
        for (int gg = 0; gg < 8; gg++) {
            float p = e[gg] * inv;
            float4 v0 = kv[512 + gg * 64 + lid * 2];
            float4 v1 = kv[512 + gg * 64 + lid * 2 + 1];
            f[0] += p * v0.x; f[1] += p * v0.y; f[2] += p * v0.z; f[3] += p * v0.w;
            f[4] += p * v1.x; f[5] += p * v1.y; f[6] += p * v1.z; f[7] += p * v1.w;
        }
        // write 3-term split directly: [hi|hi|lo]
        uint4 H, L;
        float r[8];
#pragma unroll
        for (int j = 0; j < 8; j++) {
            __nv_bfloat16 hb = __float2bfloat16_rn(f[j]);
            r[j] = f[j] - __bfloat162float(hb);
        }
        H.x = pack_bf16x2(f[0], f[1]); H.y = pack_bf16x2(f[2], f[3]);
        H.z = pack_bf16x2(f[4], f[5]); H.w = pack_bf16x2(f[6], f[7]);
        L.x = pack_bf16x2(r[0], r[1]); L.y = pack_bf16x2(r[2], r[3]);
        L.z = pack_bf16x2(r[4], r[5]); L.w = pack_bf16x2(r[6], r[7]);
        size_t base = (size_t)t * K3 + h * 256 + lid * 8;
        *(uint4*)(AOS + base) = H;
        *(uint4*)(AOS + base + C_DIM) = H;
        *(uint4*)(AOS + base + 2 * C_DIM) = L;
    }
}

// -------- launch --------
extern "C" void kernel_launch(void* const* d_in, const int* in_sizes, int n_in,
                              void* d_out, int out_size) {
    (void)in_sizes; (void)n_in; (void)out_size;
    const float* x  = (const float*)d_in[0];
    const float* y  = (const float*)d_in[1];
    const float* Wq = (const float*)d_in[2];
    const float* bq = (const float*)d_in[3];
    const float* Wk = (const float*)d_in[4];
    const float* bk = (const float*)d_in[5];
    const float* Wv = (const float*)d_in[6];
    const float* bv = (const float*)d_in[7];
    const float* Wo = (const float*)d_in[8];
    const float* bo = (const float*)d_in[9];
    float* out = (float*)d_out;

    cudaFuncSetAttribute(gemm_kernel, cudaFuncAttributeMaxDynamicSharedMemorySize, GEMM_SMEM);

    __nv_bfloat16 *xs, *ys, *aos, *wq, *wkv, *wo;
    float *q, *kv, *bkv;
    cudaGetSymbolAddress((void**)&xs,  g_xs);
    cudaGetSymbolAddress((void**)&ys,  g_ys);
    cudaGetSymbolAddress((void**)&aos, g_aos);
    cudaGetSymbolAddress((void**)&wq,  g_wq);
    cudaGetSymbolAddress((void**)&wkv, g_wkv);
    cudaGetSymbolAddress((void**)&wo,  g_wo);
    cudaGetSymbolAddress((void**)&q,   g_q);
    cudaGetSymbolAddress((void**)&kv,  g_kv);
    cudaGetSymbolAddress((void**)&bkv, g_bkv);

    const int actBlocks = (T_TOK * C_DIM) / 256;   // 65536
    const int wgtBlocks = (C_DIM * C_DIM) / 256;   // 16384

    split_act_kernel<<<actBlocks, 256>>>(x, xs);
    split_act_kernel<<<actBlocks, 256>>>(y, ys);
    split_wgt_kernel<<<wgtBlocks, 256>>>(Wq, wq);
    split_wgt_kernel<<<wgtBlocks, 256>>>(Wk, wkv);
    split_wgt_kernel<<<wgtBlocks, 256>>>(Wv, wkv + (size_t)C_DIM * K3);
    split_wgt_kernel<<<wgtBlocks, 256>>>(Wo, wo);
    concat_bias_kernel<<<16, 256>>>(bk, bv, bkv);

    dim3 gq(C_DIM / BN, T_TOK / BM);        // (8, 64)
    gemm_kernel<<<gq, 256, GEMM_SMEM>>>(xs, wq, bq, nullptr, q, C_DIM);
    dim3 gkv(2 * C_DIM / BN, T_TOK / BM);   // (16, 64)
    gemm_kernel<<<gkv, 256, GEMM_SMEM>>>(ys, wkv, bkv, nullptr, kv, 2 * C_DIM);

    attention_kernel<<<T_TOK / 8, 256>>>(q, kv, aos);

    gemm_kernel<<<gq, 256, GEMM_SMEM>>>(aos, wo, bo, x, out, C_DIM);
}

// round 6
// speedup vs baseline: 1.1583x; 1.1025x over previous
#include <cuda_runtime.h>
#include <cuda_bf16.h>
#include <cstdint>

static constexpr int T_TOK = 8192;
static constexpr int C_DIM = 2048;
static constexpr int K3 = 3 * C_DIM;       // 6144
static constexpr int BM = 128;
static constexpr int BN = 256;
static constexpr int BK = 64;              // bf16 per K-chunk
static constexpr int NKCH = K3 / BK;       // 96
static constexpr int ROW_BYTES = 144;      // 128B data + 16B pad (conflict-free ldmatrix)
static constexpr int AROWS = BM;
static constexpr int STAGE_ROWS = BM + BN; // 384
static constexpr int STAGE_BYTES = STAGE_ROWS * ROW_BYTES;  // 55296
static constexpr int STAGES = 4;
static constexpr int GEMM_SMEM = STAGES * STAGE_BYTES;      // 221184

// -------- scratch (static __device__; no allocation allowed) --------
__device__ __nv_bfloat16 g_xs [(size_t)T_TOK * K3];
__device__ __nv_bfloat16 g_ys [(size_t)T_TOK * K3];
__device__ __nv_bfloat16 g_aos[(size_t)T_TOK * K3];
__device__ __nv_bfloat16 g_wq [(size_t)C_DIM * K3];
__device__ __nv_bfloat16 g_wkv[(size_t)(2 * C_DIM) * K3];
__device__ __nv_bfloat16 g_wo [(size_t)C_DIM * K3];
__device__ float g_q  [(size_t)T_TOK * C_DIM];
__device__ float g_kv [(size_t)T_TOK * 2 * C_DIM];
__device__ float g_bkv[2 * C_DIM];

// -------- PTX helpers (sm_80+ only; no 'a'-suffix features) --------
__device__ __forceinline__ uint32_t smem_u32(const void* p) {
    uint32_t a;
    asm("{ .reg .u64 t; cvta.to.shared.u64 t, %1; cvt.u32.u64 %0, t; }" : "=r"(a) : "l"(p));
    return a;
}
#define CP_ASYNC16(s, g) \
    asm volatile("cp.async.cg.shared.global [%0], [%1], 16;" :: "r"((uint32_t)(s)), "l"(g) : "memory")
#define CP_COMMIT() asm volatile("cp.async.commit_group;" ::: "memory")

#define LDSM4(r, addr) \
    asm volatile("ldmatrix.sync.aligned.m8n8.x4.shared.b16 {%0,%1,%2,%3}, [%4];" \
        : "=r"((r)[0]), "=r"((r)[1]), "=r"((r)[2]), "=r"((r)[3]) : "r"(addr))

#define MMA16816(d, a, b0, b1) \
    asm volatile("mma.sync.aligned.m16n8k16.row.col.f32.bf16.bf16.f32 " \
        "{%0,%1,%2,%3}, {%4,%5,%6,%7}, {%8,%9}, {%0,%1,%2,%3};" \
        : "+f"((d)[0]), "+f"((d)[1]), "+f"((d)[2]), "+f"((d)[3]) \
        : "r"((a)[0]), "r"((a)[1]), "r"((a)[2]), "r"((a)[3]), "r"(b0), "r"(b1))

__device__ __forceinline__ uint32_t pack_bf16x2(float x, float y) {
    __nv_bfloat162 h = __floats2bfloat162_rn(x, y);
    return *(uint32_t*)&h;
}

// -------- fused split conversions --------
// acts: fp32 -> [hi|hi|lo]; grid.y selects x or y
__global__ void split_acts_kernel(const float* __restrict__ x, const float* __restrict__ y,
                                  __nv_bfloat16* __restrict__ xs, __nv_bfloat16* __restrict__ ys) {
    const float* src = blockIdx.y ? y : x;
    __nv_bfloat16* dst = blockIdx.y ? ys : xs;
    size_t i = (size_t)blockIdx.x * blockDim.x + threadIdx.x;
    int r = (int)(i >> 11);
    int c = (int)(i & (C_DIM - 1));
    float v = src[i];
    __nv_bfloat16 hi = __float2bfloat16_rn(v);
    __nv_bfloat16 lo = __float2bfloat16_rn(v - __bfloat162float(hi));
    size_t o = (size_t)r * K3 + c;
    dst[o] = hi; dst[o + C_DIM] = hi; dst[o + 2 * C_DIM] = lo;
}
// weights: fp32 -> [hi|lo|hi]; grid.y in {0:Wq,1:Wk,2:Wv,3:Wo}
__global__ void split_wgts_kernel(const float* __restrict__ Wq, const float* __restrict__ Wk,
                                  const float* __restrict__ Wv, const float* __restrict__ Wo,
                                  __nv_bfloat16* __restrict__ wq, __nv_bfloat16* __restrict__ wkv,
                                  __nv_bfloat16* __restrict__ wo) {
    int sel = blockIdx.y;
    const float* src = (sel == 0) ? Wq : (sel == 1) ? Wk : (sel == 2) ? Wv : Wo;
    __nv_bfloat16* dst = (sel == 0) ? wq : (sel == 1) ? wkv
                       : (sel == 2) ? wkv + (size_t)C_DIM * K3 : wo;
    size_t i = (size_t)blockIdx.x * blockDim.x + threadIdx.x;
    int r = (int)(i >> 11);
    int c = (int)(i & (C_DIM - 1));
    float v = src[i];
    __nv_bfloat16 hi = __float2bfloat16_rn(v);
    __nv_bfloat16 lo = __float2bfloat16_rn(v - __bfloat162float(hi));
    size_t o = (size_t)r * K3 + c;
    dst[o] = hi; dst[o + C_DIM] = lo; dst[o + 2 * C_DIM] = hi;
}
__global__ void concat_bias_kernel(const float* __restrict__ bk,
                                   const float* __restrict__ bv,
                                   float* __restrict__ dst) {
    int i = blockIdx.x * blockDim.x + threadIdx.x;
    dst[i] = (i < C_DIM) ? bk[i] : bv[i - C_DIM];
}

// -------- HMMA GEMM core: C[M,N] = A[M,K3] @ B[N,K3]^T + bias (+residual) --------
__device__ __forceinline__ void load_tiles_part(const __nv_bfloat16* __restrict__ A,
                                                const __nv_bfloat16* __restrict__ B,
                                                int rowA0, int rowB0, int k0,
                                                uint32_t sbase, int tid, int part) {
#pragma unroll
    for (int i = 3 * part; i < 3 * part + 3; i++) {   // 12 iters total, 3 per part
        int idx = i * 256 + tid;
        int row = idx >> 3;
        int c = idx & 7;
        const __nv_bfloat16* g = (row < AROWS)
            ? A + (size_t)(rowA0 + row) * K3 + (k0 + c * 8)
            : B + (size_t)(rowB0 + row - AROWS) * K3 + (k0 + c * 8);
        CP_ASYNC16(sbase + row * ROW_BYTES + c * 16, g);
    }
}
__device__ __forceinline__ void load_tiles(const __nv_bfloat16* __restrict__ A,
                                           const __nv_bfloat16* __restrict__ B,
                                           int rowA0, int rowB0, int k0,
                                           uint32_t sbase, int tid) {
#pragma unroll
    for (int p = 0; p < 4; p++)
        load_tiles_part(A, B, rowA0, rowB0, k0, sbase, tid, p);
}

__device__ __forceinline__ void gemm_core(const __nv_bfloat16* __restrict__ A,
                                          const __nv_bfloat16* __restrict__ B,
                                          const float* __restrict__ bias,
                                          const float* __restrict__ residual,
                                          float* __restrict__ Cout, int ldc,
                                          int rowA0, int rowB0, char* smem) {
    uint32_t sb = smem_u32(smem);
    int tid = threadIdx.x;
    int wid = tid >> 5, lid = tid & 31;
    int warp_m = wid & 1;                   // 2 warps over M
    int warp_n = wid >> 1;                  // 4 warps over N

    float acc[4][8][4];
#pragma unroll
    for (int mi = 0; mi < 4; mi++)
#pragma unroll
        for (int ni = 0; ni < 8; ni++)
#pragma unroll
            for (int e = 0; e < 4; e++) acc[mi][ni][e] = 0.f;

#pragma unroll
    for (int s = 0; s < STAGES - 1; s++) {
        load_tiles(A, B, rowA0, rowB0, s * BK, sb + s * STAGE_BYTES, tid);
        CP_COMMIT();
    }

    uint32_t a_base = sb + (warp_m * 64 + (lid & 15)) * ROW_BYTES + ((lid >> 4) << 4);
    int g = lid >> 3;
    uint32_t b_base = sb + (AROWS + warp_n * 64 + ((g >> 1) << 3) + (lid & 7)) * ROW_BYTES
                         + ((g & 1) << 4);

    for (int k = 0; k < NKCH; k++) {
        int rem = NKCH - 1 - k;
        if (rem > STAGES - 2) rem = STAGES - 2;
        switch (rem) {
            case 0: asm volatile("cp.async.wait_group 0;" ::: "memory"); break;
            case 1: asm volatile("cp.async.wait_group 1;" ::: "memory"); break;
            default: asm volatile("cp.async.wait_group 2;" ::: "memory"); break;
        }
        __syncthreads();

        uint32_t sa  = a_base + (k % STAGES) * STAGE_BYTES;
        uint32_t sbb = b_base + (k % STAGES) * STAGE_BYTES;

        uint32_t afr[2][4][4], bfr[2][4][4];
#pragma unroll
        for (int mi = 0; mi < 4; mi++) LDSM4(afr[0][mi], sa + mi * 16 * ROW_BYTES);
#pragma unroll
        for (int ni2 = 0; ni2 < 4; ni2++) LDSM4(bfr[0][ni2], sbb + ni2 * 16 * ROW_BYTES);

        int pk = k + STAGES - 1;
        bool do_pf = (pk < NKCH);
        uint32_t pf_base = sb + (pk % STAGES) * STAGE_BYTES;
        int pf_k0 = pk * BK;

#pragma unroll
        for (int ks = 0; ks < 4; ks++) {    // 4 x k16 per BK=64
            int cur = ks & 1, nxt = cur ^ 1;
            if (ks < 3) {
#pragma unroll
                for (int mi = 0; mi < 4; mi++)
                    LDSM4(afr[nxt][mi], sa + mi * 16 * ROW_BYTES + (ks + 1) * 32);
#pragma unroll
                for (int ni2 = 0; ni2 < 4; ni2++)
                    LDSM4(bfr[nxt][ni2], sbb + ni2 * 16 * ROW_BYTES + (ks + 1) * 32);
            }
            // spread prefetch: 3 cp.asyncs per ks step
            if (do_pf) {
                load_tiles_part(A, B, rowA0, rowB0, pf_k0, pf_base, tid, ks);
                if (ks == 3) CP_COMMIT();
            }
#pragma unroll
            for (int mi = 0; mi < 4; mi++)
#pragma unroll
                for (int ni2 = 0; ni2 < 4; ni2++) {
                    MMA16816(acc[mi][2 * ni2],     afr[cur][mi], bfr[cur][ni2][0], bfr[cur][ni2][1]);
                    MMA16816(acc[mi][2 * ni2 + 1], afr[cur][mi], bfr[cur][ni2][2], bfr[cur][ni2][3]);
                }
        }
    }

    int qrow = lid >> 2, qcol = (lid & 3) * 2;
#pragma unroll
    for (int mi = 0; mi < 4; mi++) {
#pragma unroll
        for (int ni = 0; ni < 8; ni++) {
            int r0 = rowA0 + warp_m * 64 + mi * 16 + qrow;
            int col = rowB0 + warp_n * 64 + ni * 8 + qcol;
            float2 bb = *(const float2*)(bias + col);
            float2 v0 = make_float2(acc[mi][ni][0] + bb.x, acc[mi][ni][1] + bb.y);
            float2 v1 = make_float2(acc[mi][ni][2] + bb.x, acc[mi][ni][3] + bb.y);
            if (residual) {
                float2 r0v = *(const float2*)(residual + (size_t)r0 * ldc + col);
                float2 r1v = *(const float2*)(residual + (size_t)(r0 + 8) * ldc + col);
                v0.x += r0v.x; v0.y += r0v.y;
                v1.x += r1v.x; v1.y += r1v.y;
            }
            *(float2*)(Cout + (size_t)r0 * ldc + col) = v0;
            *(float2*)(Cout + (size_t)(r0 + 8) * ldc + col) = v1;
        }
    }
}

// fused Q + KV GEMM: bx < 8 -> Q tile; bx >= 8 -> KV tile
__global__ void __launch_bounds__(256, 1)
gemm_qkv_kernel(const __nv_bfloat16* __restrict__ xs, const __nv_bfloat16* __restrict__ ys,
                const __nv_bfloat16* __restrict__ wq, const __nv_bfloat16* __restrict__ wkv,
                const float* __restrict__ bq, const float* __restrict__ bkv,
                float* __restrict__ q, float* __restrict__ kv) {
    extern __shared__ __align__(16) char smem[];
    int bx = blockIdx.x;
    if (bx < 8) {
        gemm_core(xs, wq, bq, nullptr, q, C_DIM, blockIdx.y * BM, bx * BN, smem);
    } else {
        gemm_core(ys, wkv, bkv, nullptr, kv, 2 * C_DIM, blockIdx.y * BM, (bx - 8) * BN, smem);
    }
}

__global__ void __launch_bounds__(256, 1)
gemm_kernel(const __nv_bfloat16* __restrict__ A, const __nv_bfloat16* __restrict__ B,
            const float* __restrict__ bias, const float* __restrict__ residual,
            float* __restrict__ Cout, int ldc) {
    extern __shared__ __align__(16) char smem[];
    gemm_core(A, B, bias, residual, Cout, ldc, blockIdx.y * BM, blockIdx.x * BN, smem);
}

// -------- per-token [8x8] head-mixing attention; writes split bf16 directly --------
__global__ void __launch_bounds__(256)
attention_kernel(const float* __restrict__ Q, const float* __restrict__ KV,
                 __nv_bfloat16* __restrict__ AOS) {
    int lid = threadIdx.x & 31;
    int t = blockIdx.x * 8 + (threadIdx.x >> 5);
    const float4* q  = (const float4*)(Q  + (size_t)t * C_DIM);
    const float4* kv = (const float4*)(KV + (size_t)t * 2 * C_DIM);
    const float scale = 0.0625f;  // 256^-0.5

    for (int h = 0; h < 8; h++) {
        float4 q0 = q[h * 64 + lid * 2];
        float4 q1 = q[h * 64 + lid * 2 + 1];
        float s[8];
#pragma unroll
        for (int gg = 0; gg < 8; gg++) {
            float4 k0 = kv[gg * 64 + lid * 2];
            float4 k1 = kv[gg * 64 + lid * 2 + 1];
            float d = q0.x * k0.x + q0.y * k0.y + q0.z * k0.z + q0.w * k0.w
                    + q1.x * k1.x + q1.y * k1.y + q1.z * k1.z + q1.w * k1.w;
#pragma unroll
            for (int off = 16; off >= 1; off >>= 1)
                d += __shfl_xor_sync(0xffffffffu, d, off);
            s[gg] = d * scale;
        }
        float m = s[0];
#pragma unroll
        for (int gg = 1; gg < 8; gg++) m = fmaxf(m, s[gg]);
        float e[8], sum = 0.f;
#pragma unroll
        for (int gg = 0; gg < 8; gg++) { e[gg] = __expf(s[gg] - m); sum += e[gg]; }
        float inv = 1.f / sum;
        float f[8];
#pragma unroll
        for (int j = 0; j < 8; j++) f[j] = 0.f;
#pragma unroll
        for (int gg = 0; gg < 8; gg++) {
            float p = e[gg] * inv;
            float4 v0 = kv[512 + gg * 64 + lid * 2];
            float4 v1 = kv[512 + gg * 64 + lid * 2 + 1];
            f[0] += p * v0.x; f[1] += p * v0.y; f[2] += p * v0.z; f[3] += p * v0.w;
            f[4] += p * v1.x; f[5] += p * v1.y; f[6] += p * v1.z; f[7] += p * v1.w;
        }
        uint4 H, L;
        float r[8];
#pragma unroll
        for (int j = 0; j < 8; j++) {
            __nv_bfloat16 hb = __float2bfloat16_rn(f[j]);
            r[j] = f[j] - __bfloat162float(hb);
        }
        H.x = pack_bf16x2(f[0], f[1]); H.y = pack_bf16x2(f[2], f[3]);
        H.z = pack_bf16x2(f[4], f[5]); H.w = pack_bf16x2(f[6], f[7]);
        L.x = pack_bf16x2(r[0], r[1]); L.y = pack_bf16x2(r[2], r[3]);
        L.z = pack_bf16x2(r[4], r[5]); L.w = pack_bf16x2(r[6], r[7]);
        size_t base = (size_t)t * K3 + h * 256 + lid * 8;
        *(uint4*)(AOS + base) = H;
        *(uint4*)(AOS + base + C_DIM) = H;
        *(uint4*)(AOS + base + 2 * C_DIM) = L;
    }
}

// -------- launch --------
extern "C" void kernel_launch(void* const* d_in, const int* in_sizes, int n_in,
                              void* d_out, int out_size) {
    (void)in_sizes; (void)n_in; (void)out_size;
    const float* x  = (const float*)d_in[0];
    const float* y  = (const float*)d_in[1];
    const float* Wq = (const float*)d_in[2];
    const float* bq = (const float*)d_in[3];
    const float* Wk = (const float*)d_in[4];
    const float* bk = (const float*)d_in[5];
    const float* Wv = (const float*)d_in[6];
    const float* bv = (const float*)d_in[7];
    const float* Wo = (const float*)d_in[8];
    const float* bo = (const float*)d_in[9];
    float* out = (float*)d_out;

    cudaFuncSetAttribute(gemm_kernel, cudaFuncAttributeMaxDynamicSharedMemorySize, GEMM_SMEM);
    cudaFuncSetAttribute(gemm_qkv_kernel, cudaFuncAttributeMaxDynamicSharedMemorySize, GEMM_SMEM);

    __nv_bfloat16 *xs, *ys, *aos, *wq, *wkv, *wo;
    float *q, *kv, *bkv;
    cudaGetSymbolAddress((void**)&xs,  g_xs);
    cudaGetSymbolAddress((void**)&ys,  g_ys);
    cudaGetSymbolAddress((void**)&aos, g_aos);
    cudaGetSymbolAddress((void**)&wq,  g_wq);
    cudaGetSymbolAddress((void**)&wkv, g_wkv);
    cudaGetSymbolAddress((void**)&wo,  g_wo);
    cudaGetSymbolAddress((void**)&q,   g_q);
    cudaGetSymbolAddress((void**)&kv,  g_kv);
    cudaGetSymbolAddress((void**)&bkv, g_bkv);

    const int actBlocks = (T_TOK * C_DIM) / 256;   // 32768 per tensor
    const int wgtBlocks = (C_DIM * C_DIM) / 256;   // 16384 per tensor

    // launch order chosen so ncu (-s 5) profiles the O GEMM (index 5)
    concat_bias_kernel<<<16, 256>>>(bk, bv, bkv);                            // 0
    split_acts_kernel<<<dim3(actBlocks, 2), 256>>>(x, y, xs, ys);            // 1
    split_wgts_kernel<<<dim3(wgtBlocks, 4), 256>>>(Wq, Wk, Wv, Wo,
                                                   wq, wkv, wo);             // 2
    gemm_qkv_kernel<<<dim3(24, 64), 256, GEMM_SMEM>>>(xs, ys, wq, wkv,
                                                      bq, bkv, q, kv);       // 3
    attention_kernel<<<T_TOK / 8, 256>>>(q, kv, aos);                        // 4
    gemm_kernel<<<dim3(8, 64), 256, GEMM_SMEM>>>(aos, wo, bo, x, out, C_DIM);// 5
}

// round 7
// speedup vs baseline: 1.1587x; 1.0004x over previous
#include <cuda_runtime.h>
#include <cuda_bf16.h>
#include <cstdint>

static constexpr int T_TOK = 8192;
static constexpr int C_DIM = 2048;
static constexpr int K3 = 3 * C_DIM;       // 6144
static constexpr int BM = 128;
static constexpr int BN = 256;
static constexpr int BK = 64;              // bf16 per K-chunk
static constexpr int NKCH = K3 / BK;       // 96
static constexpr int ROW_BYTES = 144;      // 128B data + 16B pad (conflict-free ldmatrix)
static constexpr int AROWS = BM;
static constexpr int STAGE_ROWS = BM + BN; // 384
static constexpr int STAGE_BYTES = STAGE_ROWS * ROW_BYTES;  // 55296
static constexpr int STAGES = 4;
static constexpr int GEMM_SMEM = STAGES * STAGE_BYTES;      // 221184
static constexpr int GTHREADS = 512;       // 16 warps: 2 over M x 8 over N

// -------- scratch (static __device__; no allocation allowed) --------
__device__ __nv_bfloat16 g_xs [(size_t)T_TOK * K3];
__device__ __nv_bfloat16 g_ys [(size_t)T_TOK * K3];
__device__ __nv_bfloat16 g_aos[(size_t)T_TOK * K3];
__device__ __nv_bfloat16 g_wq [(size_t)C_DIM * K3];
__device__ __nv_bfloat16 g_wkv[(size_t)(2 * C_DIM) * K3];
__device__ __nv_bfloat16 g_wo [(size_t)C_DIM * K3];
__device__ float g_q  [(size_t)T_TOK * C_DIM];
__device__ float g_kv [(size_t)T_TOK * 2 * C_DIM];
__device__ float g_bkv[2 * C_DIM];

// -------- PTX helpers (sm_80+ only; no 'a'-suffix features) --------
__device__ __forceinline__ uint32_t smem_u32(const void* p) {
    uint32_t a;
    asm("{ .reg .u64 t; cvta.to.shared.u64 t, %1; cvt.u32.u64 %0, t; }" : "=r"(a) : "l"(p));
    return a;
}
#define CP_ASYNC16(s, g) \
    asm volatile("cp.async.cg.shared.global [%0], [%1], 16;" :: "r"((uint32_t)(s)), "l"(g) : "memory")
#define CP_COMMIT() asm volatile("cp.async.commit_group;" ::: "memory")

#define LDSM4(r, addr) \
    asm volatile("ldmatrix.sync.aligned.m8n8.x4.shared.b16 {%0,%1,%2,%3}, [%4];" \
        : "=r"((r)[0]), "=r"((r)[1]), "=r"((r)[2]), "=r"((r)[3]) : "r"(addr))

#define MMA16816(d, a, b0, b1) \
    asm volatile("mma.sync.aligned.m16n8k16.row.col.f32.bf16.bf16.f32 " \
        "{%0,%1,%2,%3}, {%4,%5,%6,%7}, {%8,%9}, {%0,%1,%2,%3};" \
        : "+f"((d)[0]), "+f"((d)[1]), "+f"((d)[2]), "+f"((d)[3]) \
        : "r"((a)[0]), "r"((a)[1]), "r"((a)[2]), "r"((a)[3]), "r"(b0), "r"(b1))

__device__ __forceinline__ uint32_t pack_bf16x2(float x, float y) {
    __nv_bfloat162 h = __floats2bfloat162_rn(x, y);
    return *(uint32_t*)&h;
}

// -------- fused split conversions --------
__global__ void split_acts_kernel(const float* __restrict__ x, const float* __restrict__ y,
                                  __nv_bfloat16* __restrict__ xs, __nv_bfloat16* __restrict__ ys) {
    const float* src = blockIdx.y ? y : x;
    __nv_bfloat16* dst = blockIdx.y ? ys : xs;
    size_t i = (size_t)blockIdx.x * blockDim.x + threadIdx.x;
    int r = (int)(i >> 11);
    int c = (int)(i & (C_DIM - 1));
    float v = src[i];
    __nv_bfloat16 hi = __float2bfloat16_rn(v);
    __nv_bfloat16 lo = __float2bfloat16_rn(v - __bfloat162float(hi));
    size_t o = (size_t)r * K3 + c;
    dst[o] = hi; dst[o + C_DIM] = hi; dst[o + 2 * C_DIM] = lo;
}
__global__ void split_wgts_kernel(const float* __restrict__ Wq, const float* __restrict__ Wk,
                                  const float* __restrict__ Wv, const float* __restrict__ Wo,
                                  __nv_bfloat16* __restrict__ wq, __nv_bfloat16* __restrict__ wkv,
                                  __nv_bfloat16* __restrict__ wo) {
    int sel = blockIdx.y;
    const float* src = (sel == 0) ? Wq : (sel == 1) ? Wk : (sel == 2) ? Wv : Wo;
    __nv_bfloat16* dst = (sel == 0) ? wq : (sel == 1) ? wkv
                       : (sel == 2) ? wkv + (size_t)C_DIM * K3 : wo;
    size_t i = (size_t)blockIdx.x * blockDim.x + threadIdx.x;
    int r = (int)(i >> 11);
    int c = (int)(i & (C_DIM - 1));
    float v = src[i];
    __nv_bfloat16 hi = __float2bfloat16_rn(v);
    __nv_bfloat16 lo = __float2bfloat16_rn(v - __bfloat162float(hi));
    size_t o = (size_t)r * K3 + c;
    dst[o] = hi; dst[o + C_DIM] = lo; dst[o + 2 * C_DIM] = hi;
}
__global__ void concat_bias_kernel(const float* __restrict__ bk,
                                   const float* __restrict__ bv,
                                   float* __restrict__ dst) {
    int i = blockIdx.x * blockDim.x + threadIdx.x;
    dst[i] = (i < C_DIM) ? bk[i] : bv[i - C_DIM];
}

// -------- HMMA GEMM core (512 threads): C = A[M,K3] @ B[N,K3]^T + bias (+res) --------
__device__ __forceinline__ void load_tiles_part(const __nv_bfloat16* __restrict__ A,
                                                const __nv_bfloat16* __restrict__ B,
                                                int rowA0, int rowB0, int k0,
                                                uint32_t sbase, int tid, int part) {
    // 3072 x 16B chunks / 512 threads = 6 iters; parts: {0,1},{2,3},{4,5},{}
    if (part >= 3) return;
#pragma unroll
    for (int i = 2 * part; i < 2 * part + 2; i++) {
        int idx = i * GTHREADS + tid;
        int row = idx >> 3;
        int c = idx & 7;
        const __nv_bfloat16* g = (row < AROWS)
            ? A + (size_t)(rowA0 + row) * K3 + (k0 + c * 8)
            : B + (size_t)(rowB0 + row - AROWS) * K3 + (k0 + c * 8);
        CP_ASYNC16(sbase + row * ROW_BYTES + c * 16, g);
    }
}
__device__ __forceinline__ void load_tiles(const __nv_bfloat16* __restrict__ A,
                                           const __nv_bfloat16* __restrict__ B,
                                           int rowA0, int rowB0, int k0,
                                           uint32_t sbase, int tid) {
#pragma unroll
    for (int p = 0; p < 3; p++)
        load_tiles_part(A, B, rowA0, rowB0, k0, sbase, tid, p);
}

__device__ __forceinline__ void gemm_core(const __nv_bfloat16* __restrict__ A,
                                          const __nv_bfloat16* __restrict__ B,
                                          const float* __restrict__ bias,
                                          const float* __restrict__ residual,
                                          float* __restrict__ Cout, int ldc,
                                          int rowA0, int rowB0, char* smem) {
    uint32_t sb = smem_u32(smem);
    int tid = threadIdx.x;
    int wid = tid >> 5, lid = tid & 31;
    int warp_m = wid & 1;                   // 2 warps over M (64 rows each)
    int warp_n = wid >> 1;                  // 8 warps over N (32 cols each)

    float acc[4][4][4];
#pragma unroll
    for (int mi = 0; mi < 4; mi++)
#pragma unroll
        for (int ni = 0; ni < 4; ni++)
#pragma unroll
            for (int e = 0; e < 4; e++) acc[mi][ni][e] = 0.f;

#pragma unroll
    for (int s = 0; s < STAGES - 1; s++) {
        load_tiles(A, B, rowA0, rowB0, s * BK, sb + s * STAGE_BYTES, tid);
        CP_COMMIT();
    }

    uint32_t a_base = sb + (warp_m * 64 + (lid & 15)) * ROW_BYTES + ((lid >> 4) << 4);
    int g = lid >> 3;
    uint32_t b_base = sb + (AROWS + warp_n * 32 + ((g >> 1) << 3) + (lid & 7)) * ROW_BYTES
                         + ((g & 1) << 4);

    for (int k = 0; k < NKCH; k++) {
        int rem = NKCH - 1 - k;
        if (rem > STAGES - 2) rem = STAGES - 2;
        switch (rem) {
            case 0: asm volatile("cp.async.wait_group 0;" ::: "memory"); break;
            case 1: asm volatile("cp.async.wait_group 1;" ::: "memory"); break;
            default: asm volatile("cp.async.wait_group 2;" ::: "memory"); break;
        }
        __syncthreads();

        uint32_t sa  = a_base + (k % STAGES) * STAGE_BYTES;
        uint32_t sbb = b_base + (k % STAGES) * STAGE_BYTES;

        int pk = k + STAGES - 1;
        bool do_pf = (pk < NKCH);
        uint32_t pf_base = sb + (pk % STAGES) * STAGE_BYTES;
        int pf_k0 = pk * BK;

#pragma unroll
        for (int ks = 0; ks < 4; ks++) {    // 4 x k16 per BK=64
            uint32_t afr[4][4], bfr[2][4];
#pragma unroll
            for (int mi = 0; mi < 4; mi++)
                LDSM4(afr[mi], sa + mi * 16 * ROW_BYTES + ks * 32);
#pragma unroll
            for (int ni2 = 0; ni2 < 2; ni2++)
                LDSM4(bfr[ni2], sbb + ni2 * 16 * ROW_BYTES + ks * 32);
            // spread prefetch across ks steps
            if (do_pf) {
                load_tiles_part(A, B, rowA0, rowB0, pf_k0, pf_base, tid, ks);
                if (ks == 3) CP_COMMIT();
            }
#pragma unroll
            for (int mi = 0; mi < 4; mi++)
#pragma unroll
                for (int ni2 = 0; ni2 < 2; ni2++) {
                    MMA16816(acc[mi][2 * ni2],     afr[mi], bfr[ni2][0], bfr[ni2][1]);
                    MMA16816(acc[mi][2 * ni2 + 1], afr[mi], bfr[ni2][2], bfr[ni2][3]);
                }
        }
    }

    int qrow = lid >> 2, qcol = (lid & 3) * 2;
#pragma unroll
    for (int mi = 0; mi < 4; mi++) {
#pragma unroll
        for (int ni = 0; ni < 4; ni++) {
            int r0 = rowA0 + warp_m * 64 + mi * 16 + qrow;
            int col = rowB0 + warp_n * 32 + ni * 8 + qcol;
            float2 bb = *(const float2*)(bias + col);
            float2 v0 = make_float2(acc[mi][ni][0] + bb.x, acc[mi][ni][1] + bb.y);
            float2 v1 = make_float2(acc[mi][ni][2] + bb.x, acc[mi][ni][3] + bb.y);
            if (residual) {
                float2 r0v = *(const float2*)(residual + (size_t)r0 * ldc + col);
                float2 r1v = *(const float2*)(residual + (size_t)(r0 + 8) * ldc + col);
                v0.x += r0v.x; v0.y += r0v.y;
                v1.x += r1v.x; v1.y += r1v.y;
            }
            *(float2*)(Cout + (size_t)r0 * ldc + col) = v0;
            *(float2*)(Cout + (size_t)(r0 + 8) * ldc + col) = v1;
        }
    }
}

// fused Q + KV GEMM: bx < 8 -> Q tile; bx >= 8 -> KV tile
__global__ void __launch_bounds__(GTHREADS, 1)
gemm_qkv_kernel(const __nv_bfloat16* __restrict__ xs, const __nv_bfloat16* __restrict__ ys,
                const __nv_bfloat16* __restrict__ wq, const __nv_bfloat16* __restrict__ wkv,
                const float* __restrict__ bq, const float* __restrict__ bkv,
                float* __restrict__ q, float* __restrict__ kv) {
    extern __shared__ __align__(16) char smem[];
    int bx = blockIdx.x;
    if (bx < 8) {
        gemm_core(xs, wq, bq, nullptr, q, C_DIM, blockIdx.y * BM, bx * BN, smem);
    } else {
        gemm_core(ys, wkv, bkv, nullptr, kv, 2 * C_DIM, blockIdx.y * BM, (bx - 8) * BN, smem);
    }
}

__global__ void __launch_bounds__(GTHREADS, 1)
gemm_kernel(const __nv_bfloat16* __restrict__ A, const __nv_bfloat16* __restrict__ B,
            const float* __restrict__ bias, const float* __restrict__ residual,
            float* __restrict__ Cout, int ldc) {
    extern __shared__ __align__(16) char smem[];
    gemm_core(A, B, bias, residual, Cout, ldc, blockIdx.y * BM, blockIdx.x * BN, smem);
}

// -------- per-token [8x8] head-mixing attention; writes split bf16 directly --------
__global__ void __launch_bounds__(256)
attention_kernel(const float* __restrict__ Q, const float* __restrict__ KV,
                 __nv_bfloat16* __restrict__ AOS) {
    int lid = threadIdx.x & 31;
    int t = blockIdx.x * 8 + (threadIdx.x >> 5);
    const float4* q  = (const float4*)(Q  + (size_t)t * C_DIM);
    const float4* kv = (const float4*)(KV + (size_t)t * 2 * C_DIM);
    const float scale = 0.0625f;  // 256^-0.5

    for (int h = 0; h < 8; h++) {
        float4 q0 = q[h * 64 + lid * 2];
        float4 q1 = q[h * 64 + lid * 2 + 1];
        float s[8];
#pragma unroll
        for (int gg = 0; gg < 8; gg++) {
            float4 k0 = kv[gg * 64 + lid * 2];
            float4 k1 = kv[gg * 64 + lid * 2 + 1];
            float d = q0.x * k0.x + q0.y * k0.y + q0.z * k0.z + q0.w * k0.w
                    + q1.x * k1.x + q1.y * k1.y + q1.z * k1.z + q1.w * k1.w;
#pragma unroll
            for (int off = 16; off >= 1; off >>= 1)
                d += __shfl_xor_sync(0xffffffffu, d, off);
            s[gg] = d * scale;
        }
        float m = s[0];
#pragma unroll
        for (int gg = 1; gg < 8; gg++) m = fmaxf(m, s[gg]);
        float e[8], sum = 0.f;
#pragma unroll
        for (int gg = 0; gg < 8; gg++) { e[gg] = __expf(s[gg] - m); sum += e[gg]; }
        float inv = 1.f / sum;
        float f[8];
#pragma unroll
        for (int j = 0; j < 8; j++) f[j] = 0.f;
#pragma unroll
        for (int gg = 0; gg < 8; gg++) {
            float p = e[gg] * inv;
            float4 v0 = kv[512 + gg * 64 + lid * 2];
            float4 v1 = kv[512 + gg * 64 + lid * 2 + 1];
            f[0] += p * v0.x; f[1] += p * v0.y; f[2] += p * v0.z; f[3] += p * v0.w;
            f[4] += p * v1.x; f[5] += p * v1.y; f[6] += p * v1.z; f[7] += p * v1.w;
        }
        uint4 H, L;
        float r[8];
#pragma unroll
        for (int j = 0; j < 8; j++) {
            __nv_bfloat16 hb = __float2bfloat16_rn(f[j]);
            r[j] = f[j] - __bfloat162float(hb);
        }
        H.x = pack_bf16x2(f[0], f[1]); H.y = pack_bf16x2(f[2], f[3]);
        H.z = pack_bf16x2(f[4], f[5]); H.w = pack_bf16x2(f[6], f[7]);
        L.x = pack_bf16x2(r[0], r[1]); L.y = pack_bf16x2(r[2], r[3]);
        L.z = pack_bf16x2(r[4], r[5]); L.w = pack_bf16x2(r[6], r[7]);
        size_t base = (size_t)t * K3 + h * 256 + lid * 8;
        *(uint4*)(AOS + base) = H;
        *(uint4*)(AOS + base + C_DIM) = H;
        *(uint4*)(AOS + base + 2 * C_DIM) = L;
    }
}

// -------- launch --------
extern "C" void kernel_launch(void* const* d_in, const int* in_sizes, int n_in,
                              void* d_out, int out_size) {
    (void)in_sizes; (void)n_in; (void)out_size;
    const float* x  = (const float*)d_in[0];
    const float* y  = (const float*)d_in[1];
    const float* Wq = (const float*)d_in[2];
    const float* bq = (const float*)d_in[3];
    const float* Wk = (const float*)d_in[4];
    const float* bk = (const float*)d_in[5];
    const float* Wv = (const float*)d_in[6];
    const float* bv = (const float*)d_in[7];
    const float* Wo = (const float*)d_in[8];
    const float* bo = (const float*)d_in[9];
    float* out = (float*)d_out;

    cudaFuncSetAttribute(gemm_kernel, cudaFuncAttributeMaxDynamicSharedMemorySize, GEMM_SMEM);
    cudaFuncSetAttribute(gemm_qkv_kernel, cudaFuncAttributeMaxDynamicSharedMemorySize, GEMM_SMEM);

    __nv_bfloat16 *xs, *ys, *aos, *wq, *wkv, *wo;
    float *q, *kv, *bkv;
    cudaGetSymbolAddress((void**)&xs,  g_xs);
    cudaGetSymbolAddress((void**)&ys,  g_ys);
    cudaGetSymbolAddress((void**)&aos, g_aos);
    cudaGetSymbolAddress((void**)&wq,  g_wq);
    cudaGetSymbolAddress((void**)&wkv, g_wkv);
    cudaGetSymbolAddress((void**)&wo,  g_wo);
    cudaGetSymbolAddress((void**)&q,   g_q);
    cudaGetSymbolAddress((void**)&kv,  g_kv);
    cudaGetSymbolAddress((void**)&bkv, g_bkv);

    const int actBlocks = (T_TOK * C_DIM) / 256;   // 32768 per tensor
    const int wgtBlocks = (C_DIM * C_DIM) / 256;   // 16384 per tensor

    // launch order chosen so ncu (-s 5) profiles the O GEMM (index 5)
    concat_bias_kernel<<<16, 256>>>(bk, bv, bkv);                            // 0
    split_acts_kernel<<<dim3(actBlocks, 2), 256>>>(x, y, xs, ys);            // 1
    split_wgts_kernel<<<dim3(wgtBlocks, 4), 256>>>(Wq, Wk, Wv, Wo,
                                                   wq, wkv, wo);             // 2
    gemm_qkv_kernel<<<dim3(24, 64), GTHREADS, GEMM_SMEM>>>(xs, ys, wq, wkv,
                                                           bq, bkv, q, kv);  // 3
    attention_kernel<<<T_TOK / 8, 256>>>(q, kv, aos);                        // 4
    gemm_kernel<<<dim3(8, 64), GTHREADS, GEMM_SMEM>>>(aos, wo, bo, x, out,
                                                      C_DIM);                // 5
}